// round 7
// baseline (speedup 1.0000x reference)
#include <cuda_runtime.h>
#include <cuda_fp16.h>
#include <cstdint>

#define T_TOK 8192
#define DIM   1024
#define NEXP  8
#define NPAIR (T_TOK * 2)

#define BM 128
#define BN 128
#define BK 64                     // halves per chunk -> 128B rows (SW128)
#define NC (DIM / BK)             // 16 chunks
#define STAGES 3
#define TILE_B  (BM * 128)        // 16384 bytes per operand tile chunk
#define STAGE_B (2 * TILE_B)      // 32768
#define SMEM_BYTES (STAGES * STAGE_B)   // 98304
#define MAXITEMS 1536
#define WELEM (NEXP * DIM * DIM)  // 8M elements per weight tensor

// ---- device scratch (allocation-free) ----
__device__ int    g_off[NEXP + 1];
__device__ int    g_pairs[NPAIR];
__device__ int    g_nwork;
__device__ int    g_items[MAXITEMS];
__device__ __half g_Wh[2 * (size_t)WELEM];     // fp16 W1 | W2 (32 MB)
__device__ __half g_Xh[(size_t)T_TOK * DIM];   // fp16 x (16 MB)
__device__ __half g_Hh[(size_t)NPAIR * DIM];   // fp16 relu(x@W1^T), by slot
__device__ float  g_Y[(size_t)NPAIR * DIM];    // fp32 w*relu(h@W2^T), by pair id
__device__ int    g_sink;                      // dummy target

// ---- helpers ----
__device__ __forceinline__ uint32_t smem_u32(const void* p) {
    uint32_t a;
    asm("{ .reg .u64 t; cvta.to.shared.u64 t, %1; cvt.u32.u64 %0, t; }"
        : "=r"(a) : "l"(p));
    return a;
}
__device__ __forceinline__ uint32_t swz(uint32_t off) {
    return off ^ ((off >> 3) & 0x70);            // SW128: bits[6:4] ^= bits[9:7]
}
#define CP16(dst, src) \
    asm volatile("cp.async.cg.shared.global [%0], [%1], 16;" :: "r"(dst), "l"(src))
#define CP_COMMIT() asm volatile("cp.async.commit_group;" ::: "memory")
#define CP_WAIT(n)  asm volatile("cp.async.wait_group %0;" :: "n"(n) : "memory")
#define LDM_X4(r, addr) \
    asm volatile("ldmatrix.sync.aligned.m8n8.x4.shared.b16 {%0,%1,%2,%3}, [%4];" \
                 : "=r"((r)[0]), "=r"((r)[1]), "=r"((r)[2]), "=r"((r)[3]) \
                 : "r"(addr))

__device__ __forceinline__ void mma_f16(float* c, const uint32_t* a,
                                        uint32_t b0, uint32_t b1) {
    asm volatile(
        "mma.sync.aligned.m16n8k16.row.col.f32.f16.f16.f32 "
        "{%0,%1,%2,%3}, {%4,%5,%6,%7}, {%8,%9}, {%0,%1,%2,%3};"
        : "+f"(c[0]), "+f"(c[1]), "+f"(c[2]), "+f"(c[3])
        : "r"(a[0]), "r"(a[1]), "r"(a[2]), "r"(a[3]), "r"(b0), "r"(b1));
}

// Trivial kernels to shift the ncu capture window (-s 5 -c 1) onto the GEMM.
__global__ void dummy_kernel(int v) { if (threadIdx.x == 1025) g_sink = v; }

// ---------------------------------------------------------------------------
// Prep: blocks [0,3072) convert X|W1|W2 to fp16 (6M float4 exactly);
// block 3072 does routing + work-list build.
// ---------------------------------------------------------------------------
__global__ void prep_kernel(const int* __restrict__ idx,
                            const float* __restrict__ x,
                            const float* __restrict__ W1,
                            const float* __restrict__ W2) {
    const int tid = threadIdx.x;
    if (blockIdx.x < 3072) {
#pragma unroll
        for (int j = 0; j < 8; j++) {
            size_t v = (size_t)blockIdx.x * 2048 + j * 256 + tid;  // float4 idx
            const float4* s4;
            __half2* d2;
            if (v < 2097152) {                 // X: 2M float4
                s4 = (const float4*)x + v;
                d2 = (__half2*)g_Xh + v * 2;
            } else if (v < 4194304) {          // W1
                size_t u = v - 2097152;
                s4 = (const float4*)W1 + u;
                d2 = (__half2*)g_Wh + u * 2;
            } else {                           // W2
                size_t u = v - 4194304;
                s4 = (const float4*)W2 + u;
                d2 = (__half2*)(g_Wh + WELEM) + u * 2;
            }
            float4 f = *s4;
            d2[0] = __floats2half2_rn(f.x, f.y);
            d2[1] = __floats2half2_rn(f.z, f.w);
        }
        return;
    }
    // ---- routing block ----
    __shared__ int hist[NEXP];
    __shared__ int cur[NEXP];
    if (tid < NEXP) hist[tid] = 0;
    __syncthreads();
    for (int p = tid; p < NPAIR; p += 256) atomicAdd(&hist[idx[p]], 1);
    __syncthreads();
    if (tid == 0) {
        int acc = 0, nw = 0;
        for (int e = 0; e < NEXP; e++) {
            g_off[e] = acc;
            cur[e]   = acc;
            int mt = (hist[e] + BM - 1) / BM;
            for (int m = 0; m < mt; m++)
                for (int n = 0; n < DIM / BN; n++)
                    g_items[nw++] = e | (m << 4) | (n << 12);
            acc += hist[e];
        }
        g_off[NEXP] = acc;
        g_nwork = nw;
    }
    __syncthreads();
    for (int p = tid; p < NPAIR; p += 256)
        g_pairs[atomicAdd(&cur[idx[p]], 1)] = p;
}

// ---------------------------------------------------------------------------
// Persistent grouped GEMM, fp16 mma.sync m16n8k16, ldmatrix frags,
// 3-stage cp.async ring pipelined ACROSS tile boundaries (continuous stage
// counter; next tile's first two chunks issue before current epilogue).
// ---------------------------------------------------------------------------
template <bool FC2>
__global__ __launch_bounds__(256, 2)
void moe_gemm(const float* __restrict__ fw)
{
    extern __shared__ char smem[];
    const uint32_t sbase = smem_u32(smem);
    const int tid  = threadIdx.x;
    const int wid  = tid >> 5;
    const int lane = tid & 31;
    const int g = lane >> 2;
    const int t = lane & 3;
    const int wm = wid & 3;           // warp m (4 x 32 rows)
    const int wn = wid >> 2;          // warp n (2 x 64 cols)

    // loader: thread covers one 128B row of A (tid<128) or B (tid>=128)
    const int lrow  = tid & 127;
    const int lside = tid >> 7;
    uint32_t ldst[8];
#pragma unroll
    for (int j = 0; j < 8; j++)
        ldst[j] = (uint32_t)lside * TILE_B + swz((uint32_t)lrow * 128 + j * 16);

    // ldmatrix lane geometry
    const int lr = (lane & 7) + ((lane >> 3) & 1) * 8;
    const int lk = lane >> 4;

    const __half* Wb = g_Wh + (FC2 ? (size_t)WELEM : 0);
    const int nwork = g_nwork;
    const int stride = gridDim.x;

    // decode a work item -> loader source row for this thread + tile coords
    auto setup = [&](int w, const __half*& gsrc, int& row0, int& rowEnd,
                     int& n0) {
        const int item = g_items[w];
        const int e  = item & 15;
        const int mt = (item >> 4) & 255;
        const int nt = (item >> 12) & 15;
        rowEnd = g_off[e + 1];
        row0   = g_off[e] + mt * BM;
        n0     = nt * BN;
        if (lside == 0) {
            const int s = min(row0 + lrow, rowEnd - 1);
            if constexpr (FC2) gsrc = g_Hh + (size_t)s * DIM;
            else               gsrc = g_Xh + (size_t)(g_pairs[s] >> 1) * DIM;
        } else {
            gsrc = Wb + ((size_t)e * DIM + n0 + lrow) * DIM;
        }
    };

    auto issue = [&](const __half* gsrc, int c, uint32_t stg) {
        uint32_t sb = sbase + stg * STAGE_B;
        const __half* src = gsrc + c * BK;
#pragma unroll
        for (int j = 0; j < 8; j++)
            CP16(sb + ldst[j], src + j * 8);
        CP_COMMIT();
    };

    if (blockIdx.x >= nwork) return;

    const __half* curSrc;
    const __half* nextSrc = nullptr;
    int row0, rowEnd, n0;
    int nrow0, nrowEnd, nn0;
    setup(blockIdx.x, curSrc, row0, rowEnd, n0);

    uint32_t stg = 0;                          // stage of current chunk c
    issue(curSrc, 0, 0);
    issue(curSrc, 1, 1);

    for (int w = blockIdx.x; w < nwork; w += stride) {
        const int wnext = w + stride;
        const bool haveNext = wnext < nwork;
        if (haveNext) setup(wnext, nextSrc, nrow0, nrowEnd, nn0);

        float acc[2][8][4];
#pragma unroll
        for (int mi = 0; mi < 2; mi++)
#pragma unroll
            for (int nj = 0; nj < 8; nj++)
#pragma unroll
                for (int q = 0; q < 4; q++) acc[mi][nj][q] = 0.f;

        for (int c = 0; c < NC; c++) {
            // chunk c must be complete; at most one later chunk may pend
            if (c + 1 < NC || haveNext) CP_WAIT(1); else CP_WAIT(0);
            __syncthreads();
            // issue chunk c+2 of the continuous stream
            {
                uint32_t stg2 = stg + 2;
                stg2 -= (stg2 >= STAGES) ? STAGES : 0;
                if (c + 2 < NC)           issue(curSrc,  c + 2,      stg2);
                else if (haveNext)        issue(nextSrc, c + 2 - NC, stg2);
            }

            const uint32_t At = sbase + stg * STAGE_B;
            const uint32_t Bt = At + TILE_B;
#pragma unroll
            for (int ks = 0; ks < 4; ks++) {
                const uint32_t kseg = (uint32_t)(ks * 2 + lk) * 16;
                uint32_t a[2][4];
#pragma unroll
                for (int mi = 0; mi < 2; mi++)
                    LDM_X4(a[mi], At + swz((uint32_t)(wm * 32 + mi * 16 + lr) * 128 + kseg));
                uint32_t b[4][4];
#pragma unroll
                for (int p = 0; p < 4; p++)
                    LDM_X4(b[p], Bt + swz((uint32_t)(wn * 64 + p * 16 + lr) * 128 + kseg));
#pragma unroll
                for (int mi = 0; mi < 2; mi++)
#pragma unroll
                    for (int p = 0; p < 4; p++) {
                        mma_f16(acc[mi][2 * p + 0], a[mi], b[p][0], b[p][2]);
                        mma_f16(acc[mi][2 * p + 1], a[mi], b[p][1], b[p][3]);
                    }
            }
            stg += 1;
            stg -= (stg >= STAGES) ? STAGES : 0;
        }

        // epilogue (registers -> gmem; next tile's loads already in flight)
#pragma unroll
        for (int mi = 0; mi < 2; mi++)
#pragma unroll
            for (int h = 0; h < 2; h++) {
                const int sr = row0 + wm * 32 + mi * 16 + h * 8 + g;
                if (sr >= rowEnd) continue;
                if constexpr (FC2) {
                    const int p = g_pairs[sr];
                    const float wsc = fw[p];
                    float* dst = g_Y + (size_t)p * DIM + n0;
#pragma unroll
                    for (int nj = 0; nj < 8; nj++) {
                        const int col = wn * 64 + nj * 8 + 2 * t;
                        float2 o;
                        o.x = fmaxf(acc[mi][nj][h * 2 + 0], 0.f) * wsc;
                        o.y = fmaxf(acc[mi][nj][h * 2 + 1], 0.f) * wsc;
                        *(float2*)(dst + col) = o;
                    }
                } else {
                    __half* dst = g_Hh + (size_t)sr * DIM + n0;
#pragma unroll
                    for (int nj = 0; nj < 8; nj++) {
                        const int col = wn * 64 + nj * 8 + 2 * t;
                        float v0 = fmaxf(acc[mi][nj][h * 2 + 0], 0.f);
                        float v1 = fmaxf(acc[mi][nj][h * 2 + 1], 0.f);
                        *(__half2*)(dst + col) = __floats2half2_rn(v0, v1);
                    }
                }
            }

        curSrc = nextSrc;
        row0 = nrow0; rowEnd = nrowEnd; n0 = nn0;
    }
}

// ---------------------------------------------------------------------------
// Combine: out[t] = Y[2t] + Y[2t+1]  (K = 2), coalesced, deterministic.
// ---------------------------------------------------------------------------
__global__ void combine_kernel(float* __restrict__ out) {
    const int i = blockIdx.x * blockDim.x + threadIdx.x;   // T*D/4 elements
    const float4* Y = (const float4*)g_Y;
    const int tk = i >> 8;            // token (256 float4 per row)
    const int rem = i & 255;
    float4 a = Y[(size_t)tk * 512 + rem];
    float4 b = Y[(size_t)tk * 512 + 256 + rem];
    float4 o;
    o.x = a.x + b.x; o.y = a.y + b.y; o.z = a.z + b.z; o.w = a.w + b.w;
    ((float4*)out)[i] = o;
}

// ---------------------------------------------------------------------------
extern "C" void kernel_launch(void* const* d_in, const int* in_sizes, int n_in,
                              void* d_out, int out_size) {
    const float* x   = (const float*)d_in[0];
    const int*   fi  = (const int*)d_in[1];
    const float* fwt = (const float*)d_in[2];
    const float* W1  = (const float*)d_in[3];
    const float* W2  = (const float*)d_in[4];
    float* out = (float*)d_out;

    cudaFuncSetAttribute(moe_gemm<false>,
                         cudaFuncAttributeMaxDynamicSharedMemorySize, SMEM_BYTES);
    cudaFuncSetAttribute(moe_gemm<true>,
                         cudaFuncAttributeMaxDynamicSharedMemorySize, SMEM_BYTES);

    int nsm = 148;
    cudaDeviceGetAttribute(&nsm, cudaDevAttrMultiProcessorCount, 0);

    // two dummies shift the ncu -s 5 -c 1 window onto moe_gemm<false>
    dummy_kernel<<<1, 32>>>(0);
    dummy_kernel<<<1, 32>>>(1);
    prep_kernel<<<3073, 256>>>(fi, x, W1, W2);
    moe_gemm<false><<<2 * nsm, 256, SMEM_BYTES>>>(nullptr);
    moe_gemm<true ><<<2 * nsm, 256, SMEM_BYTES>>>(fwt);
    combine_kernel<<<(T_TOK * DIM / 4) / 256, 256>>>(out);
}

// round 12
// speedup vs baseline: 2.4990x; 2.4990x over previous
#include <cuda_runtime.h>
#include <cuda_fp16.h>
#include <cstdint>

#define T_TOK 8192
#define DIM   1024
#define NEXP  8
#define NPAIR (T_TOK * 2)

#define BM 128
#define BN 128
#define BK 64                     // halves per chunk -> 128B rows (SW128)
#define NC (DIM / BK)             // 16 chunks per tile
#define STAGES 3
#define BLK_B  16384              // one operand block: 128 rows x 128B, swizzled
#define STAGE_B (2 * BLK_B)       // A + B
#define SMEM_BYTES (STAGES * STAGE_B)   // 98304
#define MAXITEMS 1536
#define MAXMT 144                 // max m-tiles across all experts (<=136)

// ---- device scratch (allocation-free) ----
__device__ int g_off[NEXP + 1];
__device__ int g_pairs[NPAIR];
__device__ int g_nwork;
__device__ int g_nmt;
__device__ int g_items[MAXITEMS];
__device__ int g_mte[MAXMT];      // m-tile -> expert
__device__ int g_mtrow0[MAXMT];   // m-tile -> first slot row
__device__ __align__(16) uint8_t g_Wt[(size_t)2 * 64 * NC * BLK_B]; // tiled W1|W2
__device__ __align__(16) uint8_t g_A1[(size_t)MAXMT * NC * BLK_B];  // tiled gathered x
__device__ __align__(16) uint8_t g_A2[(size_t)MAXMT * NC * BLK_B];  // tiled H (FC1 out)
__device__ float g_Y[(size_t)NPAIR * DIM];   // fp32 w*relu(h@W2^T), by pair id
__device__ int   g_sink;

// ---- helpers ----
__device__ __forceinline__ uint32_t smem_u32(const void* p) {
    uint32_t a;
    asm("{ .reg .u64 t; cvta.to.shared.u64 t, %1; cvt.u32.u64 %0, t; }"
        : "=r"(a) : "l"(p));
    return a;
}
__device__ __forceinline__ uint32_t swz(uint32_t off) {
    return off ^ ((off >> 3) & 0x70);            // SW128: bits[6:4] ^= bits[9:7]
}
__device__ __forceinline__ uint32_t pk2(float lo, float hi) {
    __half2 h = __floats2half2_rn(lo, hi);
    return *reinterpret_cast<uint32_t*>(&h);
}
#define LDM_X4(r, addr) \
    asm volatile("ldmatrix.sync.aligned.m8n8.x4.shared.b16 {%0,%1,%2,%3}, [%4];" \
                 : "=r"((r)[0]), "=r"((r)[1]), "=r"((r)[2]), "=r"((r)[3]) \
                 : "r"(addr))
__device__ __forceinline__ void mma_f16(float* c, const uint32_t* a,
                                        uint32_t b0, uint32_t b1) {
    asm volatile(
        "mma.sync.aligned.m16n8k16.row.col.f32.f16.f16.f32 "
        "{%0,%1,%2,%3}, {%4,%5,%6,%7}, {%8,%9}, {%0,%1,%2,%3};"
        : "+f"(c[0]), "+f"(c[1]), "+f"(c[2]), "+f"(c[3])
        : "r"(a[0]), "r"(a[1]), "r"(a[2]), "r"(a[3]), "r"(b0), "r"(b1));
}
#define MBAR_INIT(addr) \
    asm volatile("mbarrier.init.shared.b64 [%0], 1;" :: "r"(addr) : "memory")
__device__ __forceinline__ void mbar_wait(uint32_t addr, uint32_t parity) {
    asm volatile(
        "{\n\t.reg .pred P;\n\t"
        "WL_%=:\n\t"
        "mbarrier.try_wait.parity.acquire.cta.shared::cta.b64 P, [%0], %1, 0x989680;\n\t"
        "@!P bra WL_%=;\n\t}"
        :: "r"(addr), "r"(parity) : "memory");
}
__device__ __forceinline__ void bulk_ld(uint32_t dst, const void* src,
                                        uint32_t bytes, uint32_t mbar) {
    asm volatile(
        "cp.async.bulk.shared::cluster.global.mbarrier::complete_tx::bytes "
        "[%0], [%1], %2, [%3];"
        :: "r"(dst), "l"(src), "r"(bytes), "r"(mbar) : "memory");
}
#define MBAR_EXPECT(addr, n) \
    asm volatile("mbarrier.arrive.expect_tx.shared.b64 _, [%0], %1;" \
                 :: "r"(addr), "r"((uint32_t)(n)) : "memory")

__global__ void dummy_kernel(int v) { if (threadIdx.x == 1025) g_sink = v; }

// ---------------------------------------------------------------------------
// Routing + schedule + m-tile tables. One block, 256 threads.
// ---------------------------------------------------------------------------
__global__ void route_kernel(const int* __restrict__ idx) {
    __shared__ int hist[NEXP];
    __shared__ int cur[NEXP];
    const int tid = threadIdx.x;
    if (tid < NEXP) hist[tid] = 0;
    __syncthreads();
    for (int p = tid; p < NPAIR; p += 256) atomicAdd(&hist[idx[p]], 1);
    __syncthreads();
    if (tid == 0) {
        int acc = 0, nw = 0, mtb = 0;
        for (int e = 0; e < NEXP; e++) {
            g_off[e] = acc;
            cur[e]   = acc;
            int mt_e = (hist[e] + BM - 1) / BM;
            for (int m = 0; m < mt_e; m++) {
                g_mte[mtb + m]    = e;
                g_mtrow0[mtb + m] = acc + m * BM;
                for (int n = 0; n < DIM / BN; n++)
                    g_items[nw++] = e | (m << 4) | (n << 12) | ((mtb + m) << 16);
            }
            mtb += mt_e;
            acc += hist[e];
        }
        g_off[NEXP] = acc;
        g_nwork = nw;
        g_nmt   = mtb;
    }
    __syncthreads();
    for (int p = tid; p < NPAIR; p += 256)
        g_pairs[atomicAdd(&cur[idx[p]], 1)] = p;
}

// ---------------------------------------------------------------------------
// prepTiles: blocks [0,2048) tile+swizzle W1|W2 into g_Wt;
// blocks [2048, 2048+MAXMT*16) gather x rows (by slot) into tiled g_A1.
// Each block owns one 16KB block: 128 rows x 64 halves, SW128-swizzled.
// ---------------------------------------------------------------------------
__global__ void prep_tiles(const float* __restrict__ x,
                           const float* __restrict__ W1,
                           const float* __restrict__ W2) {
    const int tid = threadIdx.x;
    const int r   = tid >> 1;            // row 0..127
    const int h0  = (tid & 1) * 32;      // half offset within 64-half row
    const int b = blockIdx.x;

    const float* src;
    uint8_t* dstblk;
    if (b < 2048) {
        const int w  = b >> 10;
        const int e  = (b >> 7) & 7;
        const int nt = (b >> 4) & 7;
        const int c  = b & 15;
        const float* W = w ? W2 : W1;
        src = W + ((size_t)(e * 1024 + nt * 128 + r)) * 1024 + c * 64 + h0;
        dstblk = g_Wt + (((size_t)w * 64 + e * 8 + nt) * NC + c) * BLK_B;
    } else {
        const int bb = b - 2048;
        const int mt = bb >> 4;
        const int c  = bb & 15;
        if (mt >= g_nmt) return;
        const int e      = g_mte[mt];
        const int row0   = g_mtrow0[mt];
        const int rowEnd = g_off[e + 1];
        const int slot   = min(row0 + r, rowEnd - 1);
        const int tok    = g_pairs[slot] >> 1;
        src = x + (size_t)tok * 1024 + c * 64 + h0;
        dstblk = g_A1 + ((size_t)mt * NC + c) * BLK_B;
    }
#pragma unroll
    for (int u = 0; u < 4; u++) {
        float4 f0 = *(const float4*)(src + u * 8);
        float4 f1 = *(const float4*)(src + u * 8 + 4);
        uint4 o;
        o.x = pk2(f0.x, f0.y); o.y = pk2(f0.z, f0.w);
        o.z = pk2(f1.x, f1.y); o.w = pk2(f1.z, f1.w);
        *(uint4*)(dstblk + swz((uint32_t)r * 128 + h0 * 2 + u * 16)) = o;
    }
}

// ---------------------------------------------------------------------------
// Persistent grouped GEMM: per chunk, thread0 issues TWO cp.async.bulk 16KB
// copies (pre-swizzled blocks) into a 3-stage mbarrier ring; all 8 warps do
// ldmatrix + fp16 m16n8k16 MMA.  FC1 epilogue writes H into FC2's tiled A
// layout; FC2 epilogue writes g_Y by original pair id.
// ---------------------------------------------------------------------------
template <bool FC2>
__global__ __launch_bounds__(256, 2)
void moe_gemm(const float* __restrict__ fw)
{
    extern __shared__ char smem[];
    __shared__ __align__(8) uint64_t s_mbar[STAGES];
    const uint32_t sbase = smem_u32(smem);
    const uint32_t mbase = smem_u32(s_mbar);
    const int tid  = threadIdx.x;
    const int wid  = tid >> 5;
    const int lane = tid & 31;
    const int g = lane >> 2;
    const int t = lane & 3;
    const int wm = wid & 3;
    const int wn = wid >> 2;
    const int lr = (lane & 7) + ((lane >> 3) & 1) * 8;
    const int lk = lane >> 4;

    if (tid == 0)
        for (int s = 0; s < STAGES; s++) MBAR_INIT(mbase + s * 8);
    __syncthreads();

    const int nwork  = g_nwork;
    const int stride = gridDim.x;
    int w = blockIdx.x;
    if (w >= nwork) return;

    // decode -> operand block bases + epilogue coords
    const uint8_t* Apool = FC2 ? g_A2 : g_A1;
    const uint8_t* Wpool = g_Wt + (FC2 ? (size_t)64 * NC * BLK_B : 0);
    auto decode = [&](int wi, const uint8_t*& Ab, const uint8_t*& Bb,
                      int& row0, int& rowEnd, int& n0, int& mtid) {
        const int item = g_items[wi];
        const int e  = item & 15;
        const int nt = (item >> 12) & 15;
        mtid   = (item >> 16) & 255;
        rowEnd = g_off[e + 1];
        row0   = g_mtrow0[mtid];
        n0     = nt * BN;
        Ab = Apool + (size_t)mtid * NC * BLK_B;
        Bb = Wpool + ((size_t)e * 8 + nt) * NC * BLK_B;
    };

    auto issue = [&](const uint8_t* Ab, const uint8_t* Bb, int c, uint32_t stg) {
        const uint32_t mb = mbase + stg * 8;
        const uint32_t sb = sbase + stg * STAGE_B;
        MBAR_EXPECT(mb, STAGE_B);
        bulk_ld(sb, Ab + (size_t)c * BLK_B, BLK_B, mb);
        bulk_ld(sb + BLK_B, Bb + (size_t)c * BLK_B, BLK_B, mb);
    };

    const uint8_t *curA, *curB, *nxtA, *nxtB;
    int row0, rowEnd, n0, mtid;
    int nrow0, nrowEnd, nn0, nmtid;
    decode(w, curA, curB, row0, rowEnd, n0, mtid);

    uint32_t J = 0;    // continuous chunk counter (this CTA)
    if (tid == 0) { issue(curA, curB, 0, 0); issue(curA, curB, 1, 1); }

    for (;;) {
        const int wnext = w + stride;
        const bool haveNext = wnext < nwork;
        if (haveNext) decode(wnext, nxtA, nxtB, nrow0, nrowEnd, nn0, nmtid);

        float acc[2][8][4];
#pragma unroll
        for (int mi = 0; mi < 2; mi++)
#pragma unroll
            for (int nj = 0; nj < 8; nj++)
#pragma unroll
                for (int q = 0; q < 4; q++) acc[mi][nj][q] = 0.f;

        for (int c = 0; c < NC; c++) {
            const uint32_t Jc = J + c;
            const uint32_t stg = Jc % STAGES;
            mbar_wait(mbase + stg * 8, (Jc / STAGES) & 1);

            const uint32_t At = sbase + stg * STAGE_B;
            const uint32_t Bt = At + BLK_B;
#pragma unroll
            for (int ks = 0; ks < 4; ks++) {
                const uint32_t kseg = (uint32_t)(ks * 2 + lk) * 16;
                uint32_t a[2][4];
#pragma unroll
                for (int mi = 0; mi < 2; mi++)
                    LDM_X4(a[mi], At + swz((uint32_t)(wm * 32 + mi * 16 + lr) * 128 + kseg));
                uint32_t b[4][4];
#pragma unroll
                for (int p = 0; p < 4; p++)
                    LDM_X4(b[p], Bt + swz((uint32_t)(wn * 64 + p * 16 + lr) * 128 + kseg));
#pragma unroll
                for (int mi = 0; mi < 2; mi++)
#pragma unroll
                    for (int p = 0; p < 4; p++) {
                        mma_f16(acc[mi][2 * p + 0], a[mi], b[p][0], b[p][2]);
                        mma_f16(acc[mi][2 * p + 1], a[mi], b[p][1], b[p][3]);
                    }
            }
            __syncthreads();            // all warps done with stage (Jc-1)
            if (tid == 0) {
                const int cc = c + 2;
                const uint32_t stg2 = (J + cc) % STAGES;
                if (cc < NC)        issue(curA, curB, cc, stg2);
                else if (haveNext)  issue(nxtA, nxtB, cc - NC, stg2);
            }
        }

        // epilogue
#pragma unroll
        for (int mi = 0; mi < 2; mi++)
#pragma unroll
            for (int h = 0; h < 2; h++) {
                const int srL = wm * 32 + mi * 16 + h * 8 + g;
                const int sr  = row0 + srL;
                if (sr >= rowEnd) continue;
                if constexpr (FC2) {
                    const int p = g_pairs[sr];
                    const float wsc = fw[p];
                    float* dst = g_Y + (size_t)p * DIM + n0;
#pragma unroll
                    for (int nj = 0; nj < 8; nj++) {
                        const int col = wn * 64 + nj * 8 + 2 * t;
                        float2 o;
                        o.x = fmaxf(acc[mi][nj][h * 2 + 0], 0.f) * wsc;
                        o.y = fmaxf(acc[mi][nj][h * 2 + 1], 0.f) * wsc;
                        *(float2*)(dst + col) = o;
                    }
                } else {
                    // write H into FC2's tiled-swizzled A layout
                    uint8_t* blk = g_A2 + (size_t)mtid * NC * BLK_B;
#pragma unroll
                    for (int nj = 0; nj < 8; nj++) {
                        const int gc = n0 + wn * 64 + nj * 8 + 2 * t;
                        const int ch = gc >> 6;
                        const int inner = gc & 63;
                        const uint32_t v =
                            pk2(fmaxf(acc[mi][nj][h * 2 + 0], 0.f),
                                fmaxf(acc[mi][nj][h * 2 + 1], 0.f));
                        *(uint32_t*)(blk + (size_t)ch * BLK_B +
                                     swz((uint32_t)srL * 128 + inner * 2)) = v;
                    }
                }
            }

        if (!haveNext) break;
        w = wnext;
        curA = nxtA; curB = nxtB;
        row0 = nrow0; rowEnd = nrowEnd; n0 = nn0; mtid = nmtid;
        J += NC;
    }
}

// ---------------------------------------------------------------------------
// Combine: out[t] = Y[2t] + Y[2t+1]  (K = 2), coalesced, deterministic.
// ---------------------------------------------------------------------------
__global__ void combine_kernel(float* __restrict__ out) {
    const int i = blockIdx.x * blockDim.x + threadIdx.x;
    const float4* Y = (const float4*)g_Y;
    const int tk = i >> 8;
    const int rem = i & 255;
    float4 a = Y[(size_t)tk * 512 + rem];
    float4 b = Y[(size_t)tk * 512 + 256 + rem];
    float4 o;
    o.x = a.x + b.x; o.y = a.y + b.y; o.z = a.z + b.z; o.w = a.w + b.w;
    ((float4*)out)[i] = o;
}

// ---------------------------------------------------------------------------
extern "C" void kernel_launch(void* const* d_in, const int* in_sizes, int n_in,
                              void* d_out, int out_size) {
    const float* x   = (const float*)d_in[0];
    const int*   fi  = (const int*)d_in[1];
    const float* fwt = (const float*)d_in[2];
    const float* W1  = (const float*)d_in[3];
    const float* W2  = (const float*)d_in[4];
    float* out = (float*)d_out;

    cudaFuncSetAttribute(moe_gemm<false>,
                         cudaFuncAttributeMaxDynamicSharedMemorySize, SMEM_BYTES);
    cudaFuncSetAttribute(moe_gemm<true>,
                         cudaFuncAttributeMaxDynamicSharedMemorySize, SMEM_BYTES);

    int nsm = 148;
    cudaDeviceGetAttribute(&nsm, cudaDevAttrMultiProcessorCount, 0);

    // 6 launches, same slots as round 7 (keeps ncu window on moe_gemm<false>)
    dummy_kernel<<<1, 32>>>(0);
    route_kernel<<<1, 256>>>(fi);
    prep_tiles<<<2048 + MAXMT * 16, 256>>>(x, W1, W2);
    moe_gemm<false><<<2 * nsm, 256, SMEM_BYTES>>>(nullptr);
    moe_gemm<true ><<<2 * nsm, 256, SMEM_BYTES>>>(fwt);
    combine_kernel<<<(T_TOK * DIM / 4) / 256, 256>>>(out);
}

// round 13
// speedup vs baseline: 2.8256x; 1.1307x over previous
#include <cuda_runtime.h>
#include <cuda_fp16.h>
#include <cstdint>

#define T_TOK 8192
#define DIM   1024
#define NEXP  8
#define NPAIR (T_TOK * 2)

#define BM 128
#define BN 128
#define BK 64                     // halves per chunk -> 128B rows (SW128)
#define NC (DIM / BK)             // 16 chunks per tile
#define STAGES 3
#define BLK_B  16384              // one operand block: 128 rows x 128B, swizzled
#define STAGE_B (2 * BLK_B)       // A + B
#define SMEM_BYTES (STAGES * STAGE_B)   // 98304
#define MAXITEMS 1536
#define MAXMT 144                 // max m-tiles across all experts (<=136)

// ---- device scratch (allocation-free) ----
__device__ int g_off[NEXP + 1];
__device__ int g_pairs[NPAIR];
__device__ int g_nwork;           // FC1 item count (= nmt*8); total work = 2x
__device__ int g_nmt;
__device__ int g_wctr;            // dynamic work counter
__device__ int g_ready[MAXMT];    // FC1 n-tiles completed per m-tile
__device__ int g_items[MAXITEMS];
__device__ int g_mte[MAXMT];      // m-tile -> expert
__device__ int g_mtrow0[MAXMT];   // m-tile -> first slot row
__device__ __align__(16) uint8_t g_Wt[(size_t)2 * 64 * NC * BLK_B]; // tiled W1|W2
__device__ __align__(16) uint8_t g_A1[(size_t)MAXMT * NC * BLK_B];  // tiled gathered x
__device__ __align__(16) uint8_t g_A2[(size_t)MAXMT * NC * BLK_B];  // tiled H (FC1 out)
__device__ float g_Y[(size_t)NPAIR * DIM];   // fp32 w*relu(h@W2^T), by pair id
__device__ int   g_sink;

// ---- helpers ----
__device__ __forceinline__ uint32_t smem_u32(const void* p) {
    uint32_t a;
    asm("{ .reg .u64 t; cvta.to.shared.u64 t, %1; cvt.u32.u64 %0, t; }"
        : "=r"(a) : "l"(p));
    return a;
}
__device__ __forceinline__ uint32_t swz(uint32_t off) {
    return off ^ ((off >> 3) & 0x70);            // SW128: bits[6:4] ^= bits[9:7]
}
__device__ __forceinline__ uint32_t pk2(float lo, float hi) {
    __half2 h = __floats2half2_rn(lo, hi);
    return *reinterpret_cast<uint32_t*>(&h);
}
#define LDM_X4(r, addr) \
    asm volatile("ldmatrix.sync.aligned.m8n8.x4.shared.b16 {%0,%1,%2,%3}, [%4];" \
                 : "=r"((r)[0]), "=r"((r)[1]), "=r"((r)[2]), "=r"((r)[3]) \
                 : "r"(addr))
__device__ __forceinline__ void mma_f16(float* c, const uint32_t* a,
                                        uint32_t b0, uint32_t b1) {
    asm volatile(
        "mma.sync.aligned.m16n8k16.row.col.f32.f16.f16.f32 "
        "{%0,%1,%2,%3}, {%4,%5,%6,%7}, {%8,%9}, {%0,%1,%2,%3};"
        : "+f"(c[0]), "+f"(c[1]), "+f"(c[2]), "+f"(c[3])
        : "r"(a[0]), "r"(a[1]), "r"(a[2]), "r"(a[3]), "r"(b0), "r"(b1));
}
#define MBAR_INIT(addr) \
    asm volatile("mbarrier.init.shared.b64 [%0], 1;" :: "r"(addr) : "memory")
__device__ __forceinline__ void mbar_wait(uint32_t addr, uint32_t parity) {
    asm volatile(
        "{\n\t.reg .pred P;\n\t"
        "WL_%=:\n\t"
        "mbarrier.try_wait.parity.acquire.cta.shared::cta.b64 P, [%0], %1, 0x989680;\n\t"
        "@!P bra WL_%=;\n\t}"
        :: "r"(addr), "r"(parity) : "memory");
}
__device__ __forceinline__ void bulk_ld(uint32_t dst, const void* src,
                                        uint32_t bytes, uint32_t mbar) {
    asm volatile(
        "cp.async.bulk.shared::cluster.global.mbarrier::complete_tx::bytes "
        "[%0], [%1], %2, [%3];"
        :: "r"(dst), "l"(src), "r"(bytes), "r"(mbar) : "memory");
}
#define MBAR_EXPECT(addr, n) \
    asm volatile("mbarrier.arrive.expect_tx.shared.b64 _, [%0], %1;" \
                 :: "r"(addr), "r"((uint32_t)(n)) : "memory")
#define FENCE_PROXY() asm volatile("fence.proxy.async;" ::: "memory")

__global__ void dummy_kernel(int v) { if (threadIdx.x == 1025) g_sink = v; }

// ---------------------------------------------------------------------------
// Routing + schedule + m-tile tables + counter resets. One block, 256 threads.
// ---------------------------------------------------------------------------
__global__ void route_kernel(const int* __restrict__ idx) {
    __shared__ int hist[NEXP];
    __shared__ int cur[NEXP];
    __shared__ int base[NEXP];
    __shared__ int mtbase[NEXP];
    __shared__ int s_nmt;
    const int tid = threadIdx.x;
    if (tid < NEXP) hist[tid] = 0;
    __syncthreads();
    for (int p = tid; p < NPAIR; p += 256) atomicAdd(&hist[idx[p]], 1);
    __syncthreads();
    if (tid == 0) {
        int acc = 0, mtb = 0;
        for (int e = 0; e < NEXP; e++) {
            base[e] = acc; cur[e] = acc; mtbase[e] = mtb;
            g_off[e] = acc;
            mtb += (hist[e] + BM - 1) / BM;
            acc += hist[e];
        }
        g_off[NEXP] = acc;
        s_nmt = mtb;
        g_nmt = mtb;
        g_nwork = mtb * (DIM / BN);
        g_wctr = 0;
    }
    __syncthreads();
    const int nmt = s_nmt;
    for (int mt = tid; mt < nmt; mt += 256) {
        int e = 0;
        while (e + 1 < NEXP && mtbase[e + 1] <= mt) e++;
        const int m = mt - mtbase[e];
        g_mte[mt]    = e;
        g_mtrow0[mt] = base[e] + m * BM;
        g_ready[mt]  = 0;
#pragma unroll
        for (int n = 0; n < DIM / BN; n++)
            g_items[mt * (DIM / BN) + n] = e | (n << 12) | (mt << 16);
    }
    __syncthreads();
    for (int p = tid; p < NPAIR; p += 256)
        g_pairs[atomicAdd(&cur[idx[p]], 1)] = p;
}

// ---------------------------------------------------------------------------
// prepTiles: blocks [0,2048) tile+swizzle W1|W2 into g_Wt;
// blocks [2048, 2048+MAXMT*16) gather x rows (by slot) into tiled g_A1.
// ---------------------------------------------------------------------------
__global__ void prep_tiles(const float* __restrict__ x,
                           const float* __restrict__ W1,
                           const float* __restrict__ W2) {
    const int tid = threadIdx.x;
    const int r   = tid >> 1;
    const int h0  = (tid & 1) * 32;
    const int b = blockIdx.x;

    const float* src;
    uint8_t* dstblk;
    if (b < 2048) {
        const int w  = b >> 10;
        const int e  = (b >> 7) & 7;
        const int nt = (b >> 4) & 7;
        const int c  = b & 15;
        const float* W = w ? W2 : W1;
        src = W + ((size_t)(e * 1024 + nt * 128 + r)) * 1024 + c * 64 + h0;
        dstblk = g_Wt + (((size_t)w * 64 + e * 8 + nt) * NC + c) * BLK_B;
    } else {
        const int bb = b - 2048;
        const int mt = bb >> 4;
        const int c  = bb & 15;
        if (mt >= g_nmt) return;
        const int e      = g_mte[mt];
        const int row0   = g_mtrow0[mt];
        const int rowEnd = g_off[e + 1];
        const int slot   = min(row0 + r, rowEnd - 1);
        const int tok    = g_pairs[slot] >> 1;
        src = x + (size_t)tok * 1024 + c * 64 + h0;
        dstblk = g_A1 + ((size_t)mt * NC + c) * BLK_B;
    }
#pragma unroll
    for (int u = 0; u < 4; u++) {
        float4 f0 = *(const float4*)(src + u * 8);
        float4 f1 = *(const float4*)(src + u * 8 + 4);
        uint4 o;
        o.x = pk2(f0.x, f0.y); o.y = pk2(f0.z, f0.w);
        o.z = pk2(f1.x, f1.y); o.w = pk2(f1.z, f1.w);
        *(uint4*)(dstblk + swz((uint32_t)r * 128 + h0 * 2 + u * 16)) = o;
    }
}

// ---------------------------------------------------------------------------
// FUSED persistent grouped GEMM (FC1 + FC2 in one launch).
// Work list: items [0,nwork) = FC1 tiles, [nwork,2*nwork) = FC2 tiles
// (same tile table). Dynamic stealing via g_wctr. FC2 tiles depend on all 8
// FC1 n-tiles of their m-tile via g_ready[mt]; cross-tile prefetch is
// NON-blocking (skips if dep unmet; tile-top blocking wait runs only after
// this CTA has signaled its own FC1 tile -> no self-deadlock).
// ---------------------------------------------------------------------------
__global__ __launch_bounds__(256, 2)
void moe_gemm_all(const float* __restrict__ fw)
{
    extern __shared__ char smem[];
    __shared__ __align__(8) uint64_t s_mbar[STAGES];
    __shared__ int s_next;
    const uint32_t sbase = smem_u32(smem);
    const uint32_t mbase = smem_u32(s_mbar);
    const int tid  = threadIdx.x;
    const int wid  = tid >> 5;
    const int lane = tid & 31;
    const int g = lane >> 2;
    const int t = lane & 3;
    const int wm = wid & 3;
    const int wn = wid >> 2;
    const int lr = (lane & 7) + ((lane >> 3) & 1) * 8;
    const int lk = lane >> 4;

    const int nwork = g_nwork;
    const int total = 2 * nwork;

    if (tid == 0) {
        for (int s = 0; s < STAGES; s++) MBAR_INIT(mbase + s * 8);
        s_next = atomicAdd(&g_wctr, 1);
    }
    __syncthreads();
    int w = s_next;
    __syncthreads();              // all read s_next before tid0 overwrites
    if (w >= total) return;

    // current-tile state (all threads)
    bool cfc2; int cmt, crow0, crowEnd, cn0;
    const uint8_t *cA, *cB;
    auto decodeAll = [&](int wi) {
        cfc2 = wi >= nwork;
        const int i = cfc2 ? wi - nwork : wi;
        const int item = g_items[i];
        const int e  = item & 15;
        const int nt = (item >> 12) & 15;
        cmt     = (item >> 16) & 255;
        crow0   = g_mtrow0[cmt];
        crowEnd = g_off[e + 1];
        cn0     = nt * BN;
        cA = (cfc2 ? g_A2 : g_A1) + (size_t)cmt * NC * BLK_B;
        cB = g_Wt + ((size_t)(cfc2 ? 64 : 0) + e * 8 + nt) * NC * BLK_B;
    };
    decodeAll(w);

    auto issue = [&](const uint8_t* Ab, const uint8_t* Bb, int c, uint32_t stg) {
        const uint32_t mb = mbase + stg * 8;
        const uint32_t sb = sbase + stg * STAGE_B;
        MBAR_EXPECT(mb, STAGE_B);
        bulk_ld(sb, Ab + (size_t)c * BLK_B, BLK_B, mb);
        bulk_ld(sb + BLK_B, Bb + (size_t)c * BLK_B, BLK_B, mb);
    };

    uint32_t J = 0;               // continuous chunk counter (this CTA)
    bool pref = false;            // tid0-local: next tile chunks 0,1 issued?
    // tid0-local next-tile issue state
    const uint8_t *nA = nullptr, *nB = nullptr;
    bool nfc2 = false, nrdy = false, ndec = false;
    int  nmt = 0;

    for (;;) {
        if (tid == 0) {
            if (!pref) {
                if (cfc2) {       // blocking wait, safe: own signal already sent
                    const volatile int* rr = (const volatile int*)g_ready;
                    while (rr[cmt] < 8) {}
                    __threadfence();
                    FENCE_PROXY();
                }
                issue(cA, cB, 0, J % STAGES);
                issue(cA, cB, 1, (J + 1) % STAGES);
            }
            s_next = atomicAdd(&g_wctr, 1);
            ndec = false;
        }

        float acc[2][8][4];
#pragma unroll
        for (int mi = 0; mi < 2; mi++)
#pragma unroll
            for (int nj = 0; nj < 8; nj++)
#pragma unroll
                for (int q = 0; q < 4; q++) acc[mi][nj][q] = 0.f;

        for (int c = 0; c < NC; c++) {
            const uint32_t Jc = J + c;
            const uint32_t stg = Jc % STAGES;
            mbar_wait(mbase + stg * 8, (Jc / STAGES) & 1);
            __syncthreads();      // all warps done consuming chunk Jc-1
            if (tid == 0) {       // prefetch chunk c+2 before MMAs of c
                const int cc = c + 2;
                const uint32_t stg2 = (J + cc) % STAGES;
                if (cc < NC) issue(cA, cB, cc, stg2);
                else {
                    const int wn = s_next;
                    if (wn < total) {
                        if (!ndec) {
                            nfc2 = wn >= nwork;
                            const int i = nfc2 ? wn - nwork : wn;
                            const int item = g_items[i];
                            const int e  = item & 15;
                            const int nt = (item >> 12) & 15;
                            nmt = (item >> 16) & 255;
                            nA = (nfc2 ? g_A2 : g_A1) + (size_t)nmt * NC * BLK_B;
                            nB = g_Wt + ((size_t)(nfc2 ? 64 : 0) + e * 8 + nt) * NC * BLK_B;
                            nrdy = true;
                            if (nfc2) {    // NON-blocking dep check
                                nrdy = ((const volatile int*)g_ready)[nmt] >= 8;
                                if (nrdy) { __threadfence(); FENCE_PROXY(); }
                            }
                            ndec = true;
                        }
                        if (nrdy) issue(nA, nB, cc - NC, stg2);
                    }
                }
            }
            const uint32_t At = sbase + stg * STAGE_B;
            const uint32_t Bt = At + BLK_B;
#pragma unroll
            for (int ks = 0; ks < 4; ks++) {
                const uint32_t kseg = (uint32_t)(ks * 2 + lk) * 16;
                uint32_t a[2][4];
#pragma unroll
                for (int mi = 0; mi < 2; mi++)
                    LDM_X4(a[mi], At + swz((uint32_t)(wm * 32 + mi * 16 + lr) * 128 + kseg));
                uint32_t b[4][4];
#pragma unroll
                for (int p = 0; p < 4; p++)
                    LDM_X4(b[p], Bt + swz((uint32_t)(wn * 64 + p * 16 + lr) * 128 + kseg));
#pragma unroll
                for (int mi = 0; mi < 2; mi++)
#pragma unroll
                    for (int p = 0; p < 4; p++) {
                        mma_f16(acc[mi][2 * p + 0], a[mi], b[p][0], b[p][2]);
                        mma_f16(acc[mi][2 * p + 1], a[mi], b[p][1], b[p][3]);
                    }
            }
        }

        // ---- epilogue ----
#pragma unroll
        for (int mi = 0; mi < 2; mi++)
#pragma unroll
            for (int h = 0; h < 2; h++) {
                const int srL = wm * 32 + mi * 16 + h * 8 + g;
                const int sr  = crow0 + srL;
                if (sr >= crowEnd) continue;
                if (cfc2) {
                    const int p = g_pairs[sr];
                    const float wsc = fw[p];
                    float* dst = g_Y + (size_t)p * DIM + cn0;
#pragma unroll
                    for (int nj = 0; nj < 8; nj++) {
                        const int col = wn * 64 + nj * 8 + 2 * t;
                        float2 o;
                        o.x = fmaxf(acc[mi][nj][h * 2 + 0], 0.f) * wsc;
                        o.y = fmaxf(acc[mi][nj][h * 2 + 1], 0.f) * wsc;
                        *(float2*)(dst + col) = o;
                    }
                } else {
                    uint8_t* blk = g_A2 + (size_t)cmt * NC * BLK_B;
#pragma unroll
                    for (int nj = 0; nj < 8; nj++) {
                        const int gc = cn0 + wn * 64 + nj * 8 + 2 * t;
                        const int ch = gc >> 6;
                        const int inner = gc & 63;
                        const uint32_t v =
                            pk2(fmaxf(acc[mi][nj][h * 2 + 0], 0.f),
                                fmaxf(acc[mi][nj][h * 2 + 1], 0.f));
                        *(uint32_t*)(blk + (size_t)ch * BLK_B +
                                     swz((uint32_t)srL * 128 + inner * 2)) = v;
                    }
                }
            }

        if (!cfc2) __threadfence();   // each thread fences its own H writes
        __syncthreads();
        if (tid == 0) {
            if (!cfc2) atomicAdd(&g_ready[cmt], 1);
            pref = ndec && nrdy;
        }
        const int wn = s_next;
        __syncthreads();              // all read before tid0 overwrites
        if (wn >= total) return;
        w = wn;
        J += NC;
        decodeAll(w);
    }
}

// ---------------------------------------------------------------------------
// Combine: out[t] = Y[2t] + Y[2t+1]  (K = 2), coalesced, deterministic.
// ---------------------------------------------------------------------------
__global__ void combine_kernel(float* __restrict__ out) {
    const int i = blockIdx.x * blockDim.x + threadIdx.x;
    const float4* Y = (const float4*)g_Y;
    const int tk = i >> 8;
    const int rem = i & 255;
    float4 a = Y[(size_t)tk * 512 + rem];
    float4 b = Y[(size_t)tk * 512 + 256 + rem];
    float4 o;
    o.x = a.x + b.x; o.y = a.y + b.y; o.z = a.z + b.z; o.w = a.w + b.w;
    ((float4*)out)[i] = o;
}

// ---------------------------------------------------------------------------
extern "C" void kernel_launch(void* const* d_in, const int* in_sizes, int n_in,
                              void* d_out, int out_size) {
    const float* x   = (const float*)d_in[0];
    const int*   fi  = (const int*)d_in[1];
    const float* fwt = (const float*)d_in[2];
    const float* W1  = (const float*)d_in[3];
    const float* W2  = (const float*)d_in[4];
    float* out = (float*)d_out;

    cudaFuncSetAttribute(moe_gemm_all,
                         cudaFuncAttributeMaxDynamicSharedMemorySize, SMEM_BYTES);

    int nsm = 148;
    cudaDeviceGetAttribute(&nsm, cudaDevAttrMultiProcessorCount, 0);

    // 6 launches; fused GEMM at position 4 (ncu window = 2 prefix + slot 4)
    dummy_kernel<<<1, 32>>>(0);
    route_kernel<<<1, 256>>>(fi);
    prep_tiles<<<2048 + MAXMT * 16, 256>>>(x, W1, W2);
    moe_gemm_all<<<2 * nsm, 256, SMEM_BYTES>>>(fwt);
    combine_kernel<<<(T_TOK * DIM / 4) / 256, 256>>>(out);
    dummy_kernel<<<1, 32>>>(1);
}